// round 2
// baseline (speedup 1.0000x reference)
#include <cuda_runtime.h>
#include <cuda_fp16.h>
#include <mma.h>

using namespace nvcuda;

// Problem constants
#define T_TOK  4096
#define D_DIM  1024
#define F_DIM  2816
#define F2_DIM 5632
#define E_NUM  8
#define K_TOP  2

#define MAXR   3072          // per-expert row capacity (mean 1024, huge margin)
#define MTILES 24            // MAXR / 128

#define LDT    40            // smem half tile stride (32 + 8 pad) -> conflict-free
#define LDS_F  72            // smem float epilogue buffer stride

// -------- device scratch (static: no allocation allowed) --------
__device__ int    g_count[E_NUM];
__device__ int    g_padded[E_NUM];
__device__ int    g_tok[E_NUM * MAXR];
__device__ float  g_wt [E_NUM * MAXR];
// fp16 intermediate h = silu(gate)*up, row slot = e*MAXR + r  (138 MB bss)
__device__ __align__(16) __half g_h[(size_t)E_NUM * MAXR * F_DIM];

// ---------------------------------------------------------------
__global__ void zero_kernel(float* __restrict__ out, int n) {
    for (int i = blockIdx.x * blockDim.x + threadIdx.x; i < n; i += gridDim.x * blockDim.x)
        out[i] = 0.f;
}

// Build per-expert token lists. Handles selected_experts as int64 OR int32
// (JAX default config silently demotes int64 -> int32; sniff the layout).
__global__ void route_kernel(const int* __restrict__ sel_raw, const float* __restrict__ rw) {
    __shared__ int s_is64;
    int tid = threadIdx.x;
    if (tid == 0) {
        // If int64 (little-endian, values 0..7), every odd 32-bit word is 0.
        int odd_or = 0;
        for (int i = 1; i < 64; i += 2) odd_or |= sel_raw[i];
        s_is64 = (odd_or == 0) ? 1 : 0;
    }
    if (tid < E_NUM) g_count[tid] = 0;
    __syncthreads();
    int is64 = s_is64;

    for (int i = tid; i < T_TOK * K_TOP; i += blockDim.x) {
        int e = is64 ? sel_raw[2 * i] : sel_raw[i];
        e &= (E_NUM - 1);                          // hard clamp: no OOB ever
        float w = rw[i];
        int pos = atomicAdd(&g_count[e], 1);
        if (pos < MAXR) {                          // hard clamp: no OOB ever
            g_tok[e * MAXR + pos] = i / K_TOP;
            g_wt [e * MAXR + pos] = w;
        }
    }
    __syncthreads();

    for (int e = 0; e < E_NUM; e++) {
        int cnt = g_count[e];
        if (cnt > MAXR) cnt = MAXR;
        int pad = (cnt + 127) & ~127;
        if (pad > MAXR) pad = MAXR;
        if (tid == 0) g_padded[e] = pad;
        for (int i = cnt + tid; i < pad; i += blockDim.x) {
            g_tok[e * MAXR + i] = 0;     // real token data -> finite math
            g_wt [e * MAXR + i] = 0.f;   // contributes exactly 0
        }
    }
}

// ---------------------------------------------------------------
// GEMM1 + SwiGLU:  h[r, n] = silu(X[tok_r] . Wgu[e][n]) * (X[tok_r] . Wgu[e][F+n])
// Block tile: 128 rows x 64 cols (of F). 8 warps = 4(m) x 2(n), warp 32x32.
__global__ __launch_bounds__(256) void gemm1_kernel(
    const float* __restrict__ X, const float* __restrict__ Wgu)
{
    __shared__ __align__(16) unsigned char smem_raw[128 * LDS_F * 4];  // 36864 B
    __half* As = (__half*)smem_raw;            // [128][LDT]
    __half* Bs = As + 128 * LDT;               // [128][LDT]  rows 0..63 gate, 64..127 up
    float*  Sf = (float*)smem_raw;             // [128][LDS_F] (epilogue, aliased)

    const int e  = blockIdx.y / MTILES;
    const int mt = blockIdx.y % MTILES;
    const int m0 = mt * 128;
    if (m0 >= g_padded[e]) return;
    const int n0 = blockIdx.x * 64;

    const int tid  = threadIdx.x;
    const int warp = tid >> 5;
    const int wm   = warp & 3;
    const int wn   = warp >> 2;

    const int arow = tid >> 1;
    const int acol = (tid & 1) * 16;
    const float* aptr = X + (size_t)g_tok[e * MAXR + m0 + arow] * D_DIM + acol;

    const int brow = tid >> 1;
    const int f = (brow < 64) ? (n0 + brow) : (F_DIM + n0 + (brow - 64));
    const float* bptr = Wgu + ((size_t)e * F2_DIM + f) * D_DIM + acol;

    wmma::fragment<wmma::accumulator, 16, 16, 16, float> cg[2][2], cu[2][2];
    #pragma unroll
    for (int i = 0; i < 2; i++)
        #pragma unroll
        for (int j = 0; j < 2; j++) {
            wmma::fill_fragment(cg[i][j], 0.f);
            wmma::fill_fragment(cu[i][j], 0.f);
        }

    for (int k0 = 0; k0 < D_DIM; k0 += 32) {
        #pragma unroll
        for (int i = 0; i < 4; i++) {
            float4 v = *(const float4*)(aptr + k0 + i * 4);
            __half2* dst = (__half2*)&As[arow * LDT + acol + i * 4];
            dst[0] = __floats2half2_rn(v.x, v.y);
            dst[1] = __floats2half2_rn(v.z, v.w);
        }
        #pragma unroll
        for (int i = 0; i < 4; i++) {
            float4 v = *(const float4*)(bptr + k0 + i * 4);
            __half2* dst = (__half2*)&Bs[brow * LDT + acol + i * 4];
            dst[0] = __floats2half2_rn(v.x, v.y);
            dst[1] = __floats2half2_rn(v.z, v.w);
        }
        __syncthreads();
        #pragma unroll
        for (int kk = 0; kk < 32; kk += 16) {
            wmma::fragment<wmma::matrix_a, 16, 16, 16, __half, wmma::row_major> a[2];
            wmma::fragment<wmma::matrix_b, 16, 16, 16, __half, wmma::col_major> bg[2], bu[2];
            #pragma unroll
            for (int i = 0; i < 2; i++)
                wmma::load_matrix_sync(a[i], &As[(wm * 32 + i * 16) * LDT + kk], LDT);
            #pragma unroll
            for (int j = 0; j < 2; j++) {
                wmma::load_matrix_sync(bg[j], &Bs[(wn * 32 + j * 16) * LDT + kk], LDT);
                wmma::load_matrix_sync(bu[j], &Bs[(64 + wn * 32 + j * 16) * LDT + kk], LDT);
            }
            #pragma unroll
            for (int i = 0; i < 2; i++)
                #pragma unroll
                for (int j = 0; j < 2; j++) {
                    wmma::mma_sync(cg[i][j], a[i], bg[j], cg[i][j]);
                    wmma::mma_sync(cu[i][j], a[i], bu[j], cu[i][j]);
                }
        }
        __syncthreads();
    }

    // SwiGLU in registers, stage through smem, write fp16 to g_h
    #pragma unroll
    for (int i = 0; i < 2; i++)
        #pragma unroll
        for (int j = 0; j < 2; j++) {
            #pragma unroll
            for (int t = 0; t < cg[i][j].num_elements; t++) {
                float g = cg[i][j].x[t];
                float u = cu[i][j].x[t];
                cg[i][j].x[t] = u * g / (1.f + __expf(-g));
            }
            wmma::store_matrix_sync(&Sf[(wm * 32 + i * 16) * LDS_F + wn * 32 + j * 16],
                                    cg[i][j], LDS_F, wmma::mem_row_major);
        }
    __syncthreads();

    const int row = tid >> 1;
    const int cb  = (tid & 1) * 32;
    __half2* hdst = (__half2*)&g_h[((size_t)(e * MAXR + m0 + row)) * F_DIM + n0 + cb];
    #pragma unroll
    for (int c = 0; c < 32; c += 2)
        hdst[c >> 1] = __floats2half2_rn(Sf[row * LDS_F + cb + c],
                                         Sf[row * LDS_F + cb + c + 1]);
}

// ---------------------------------------------------------------
// GEMM2: out[tok_r, n] += w_r * (h[r] . Wd[e][n]),  K = F = 2816
__global__ __launch_bounds__(256) void gemm2_kernel(
    const float* __restrict__ Wd, float* __restrict__ out)
{
    __shared__ __align__(16) unsigned char smem_raw[128 * LDS_F * 4];
    __half* As = (__half*)smem_raw;            // [128][LDT]
    __half* Bs = As + 128 * LDT;               // [64][LDT]
    float*  Sf = (float*)smem_raw;             // [128][LDS_F]

    const int e  = blockIdx.y / MTILES;
    const int mt = blockIdx.y % MTILES;
    const int m0 = mt * 128;
    if (m0 >= g_padded[e]) return;
    const int n0 = blockIdx.x * 64;

    const int tid  = threadIdx.x;
    const int warp = tid >> 5;
    const int wm   = warp & 3;
    const int wn   = warp >> 2;

    const int arow = tid >> 1;
    const int acg  = (tid & 1) * 16;
    const __half* aptr = g_h + (size_t)(e * MAXR + m0 + arow) * F_DIM + acg;

    const int brow = tid >> 2;          // 0..63
    const int bcg  = (tid & 3) * 8;     // 0,8,16,24
    const float* bptr = Wd + ((size_t)e * D_DIM + n0 + brow) * F_DIM + bcg;

    wmma::fragment<wmma::accumulator, 16, 16, 16, float> c[2][2];
    #pragma unroll
    for (int i = 0; i < 2; i++)
        #pragma unroll
        for (int j = 0; j < 2; j++)
            wmma::fill_fragment(c[i][j], 0.f);

    for (int k0 = 0; k0 < F_DIM; k0 += 32) {
        *(uint4*)&As[arow * LDT + acg]     = *(const uint4*)(aptr + k0);
        *(uint4*)&As[arow * LDT + acg + 8] = *(const uint4*)(aptr + k0 + 8);
        #pragma unroll
        for (int i = 0; i < 2; i++) {
            float4 v = *(const float4*)(bptr + k0 + i * 4);
            __half2* dst = (__half2*)&Bs[brow * LDT + bcg + i * 4];
            dst[0] = __floats2half2_rn(v.x, v.y);
            dst[1] = __floats2half2_rn(v.z, v.w);
        }
        __syncthreads();
        #pragma unroll
        for (int kk = 0; kk < 32; kk += 16) {
            wmma::fragment<wmma::matrix_a, 16, 16, 16, __half, wmma::row_major> a[2];
            wmma::fragment<wmma::matrix_b, 16, 16, 16, __half, wmma::col_major> b[2];
            #pragma unroll
            for (int i = 0; i < 2; i++)
                wmma::load_matrix_sync(a[i], &As[(wm * 32 + i * 16) * LDT + kk], LDT);
            #pragma unroll
            for (int j = 0; j < 2; j++)
                wmma::load_matrix_sync(b[j], &Bs[(wn * 32 + j * 16) * LDT + kk], LDT);
            #pragma unroll
            for (int i = 0; i < 2; i++)
                #pragma unroll
                for (int j = 0; j < 2; j++)
                    wmma::mma_sync(c[i][j], a[i], b[j], c[i][j]);
        }
        __syncthreads();
    }

    #pragma unroll
    for (int i = 0; i < 2; i++)
        #pragma unroll
        for (int j = 0; j < 2; j++)
            wmma::store_matrix_sync(&Sf[(wm * 32 + i * 16) * LDS_F + wn * 32 + j * 16],
                                    c[i][j], LDS_F, wmma::mem_row_major);
    __syncthreads();

    const int row = tid >> 1;
    const int cb  = (tid & 1) * 32;
    const float w = g_wt[e * MAXR + m0 + row];
    if (w != 0.f) {
        const int tok = g_tok[e * MAXR + m0 + row];
        float* o = out + (size_t)tok * D_DIM + n0 + cb;
        #pragma unroll
        for (int cc = 0; cc < 32; cc++)
            atomicAdd(o + cc, w * Sf[row * LDS_F + cb + cc]);
    }
}

// ---------------------------------------------------------------
extern "C" void kernel_launch(void* const* d_in, const int* in_sizes, int n_in,
                              void* d_out, int out_size) {
    // Robust input mapping by element count (two 8192-element arrays keep dict order:
    // routing_weights first, selected_experts second).
    const float* X = nullptr; const float* RW = nullptr;
    const float* WGU = nullptr; const float* WD = nullptr;
    const int* SEL = nullptr;
    for (int i = 0; i < n_in; i++) {
        long long n = in_sizes[i];
        if (n == (long long)T_TOK * D_DIM)               X   = (const float*)d_in[i];
        else if (n == (long long)E_NUM * F2_DIM * D_DIM) WGU = (const float*)d_in[i];
        else if (n == (long long)E_NUM * D_DIM * F_DIM)  WD  = (const float*)d_in[i];
        else if (n == (long long)T_TOK * K_TOP) {
            if (!RW) RW = (const float*)d_in[i];
            else     SEL = (const int*)d_in[i];
        }
    }
    float* out = (float*)d_out;

    zero_kernel<<<2048, 256>>>(out, T_TOK * D_DIM);
    route_kernel<<<1, 256>>>(SEL, RW);
    gemm1_kernel<<<dim3(F_DIM / 64, E_NUM * MTILES), 256>>>(X, WGU);
    gemm2_kernel<<<dim3(D_DIM / 64, E_NUM * MTILES), 256>>>(WD, out);
}

// round 3
// speedup vs baseline: 1.1185x; 1.1185x over previous
#include <cuda_runtime.h>
#include <cuda_fp16.h>
#include <mma.h>

using namespace nvcuda;

// Problem constants
#define T_TOK  4096
#define D_DIM  1024
#define F_DIM  2816
#define F2_DIM 5632
#define E_NUM  8
#define K_TOP  2

#define MAXR   3072          // per-expert row capacity
#define MTILES 24            // MAXR / 128

#define LDT    40            // smem half tile stride (32 + 8 pad), 80B = 16B-aligned
#define LDS_F  72            // smem float epilogue stride

// -------- device scratch (static: no allocation allowed) --------
__device__ int    g_count[E_NUM];
__device__ int    g_padded[E_NUM];
__device__ int    g_tok[E_NUM * MAXR];
__device__ float  g_wt [E_NUM * MAXR];
__device__ __align__(16) __half g_Xh [(size_t)T_TOK * D_DIM];           // 8 MB
__device__ __align__(16) __half g_Wgu[(size_t)E_NUM * F2_DIM * D_DIM];  // 92 MB
__device__ __align__(16) __half g_Wd [(size_t)E_NUM * D_DIM * F_DIM];   // 46 MB
__device__ __align__(16) __half g_h  [(size_t)E_NUM * MAXR * F_DIM];    // 138 MB

// -------- cp.async helpers --------
__device__ __forceinline__ unsigned smem_u32(const void* p) {
    return (unsigned)__cvta_generic_to_shared(p);
}
#define CP16(dst, src) asm volatile("cp.async.cg.shared.global [%0], [%1], 16;\n" :: "r"(dst), "l"(src))
#define CP_COMMIT()    asm volatile("cp.async.commit_group;\n")
#define CP_WAIT1()     asm volatile("cp.async.wait_group 1;\n")
#define CP_WAIT0()     asm volatile("cp.async.wait_group 0;\n")

// ---------------------------------------------------------------
__global__ void zero_kernel(float* __restrict__ out, int n) {
    for (int i = blockIdx.x * blockDim.x + threadIdx.x; i < n; i += gridDim.x * blockDim.x)
        out[i] = 0.f;
}

__global__ void cvt_kernel(const float* __restrict__ src, __half* __restrict__ dst, int n) {
    for (int i = (blockIdx.x * blockDim.x + threadIdx.x) * 8; i < n;
         i += gridDim.x * blockDim.x * 8) {
        float4 v0 = *(const float4*)(src + i);
        float4 v1 = *(const float4*)(src + i + 4);
        __half2 h[4];
        h[0] = __floats2half2_rn(v0.x, v0.y);
        h[1] = __floats2half2_rn(v0.z, v0.w);
        h[2] = __floats2half2_rn(v1.x, v1.y);
        h[3] = __floats2half2_rn(v1.z, v1.w);
        *(uint4*)(dst + i) = *(uint4*)h;
    }
}

// Build per-expert token lists; sniff int64 vs int32 selected_experts.
__global__ void route_kernel(const int* __restrict__ sel_raw, const float* __restrict__ rw) {
    __shared__ int s_is64;
    int tid = threadIdx.x;
    if (tid == 0) {
        int odd_or = 0;
        for (int i = 1; i < 64; i += 2) odd_or |= sel_raw[i];
        s_is64 = (odd_or == 0) ? 1 : 0;
    }
    if (tid < E_NUM) g_count[tid] = 0;
    __syncthreads();
    int is64 = s_is64;

    for (int i = tid; i < T_TOK * K_TOP; i += blockDim.x) {
        int e = is64 ? sel_raw[2 * i] : sel_raw[i];
        e &= (E_NUM - 1);
        float w = rw[i];
        int pos = atomicAdd(&g_count[e], 1);
        if (pos < MAXR) {
            g_tok[e * MAXR + pos] = i / K_TOP;
            g_wt [e * MAXR + pos] = w;
        }
    }
    __syncthreads();

    for (int e = 0; e < E_NUM; e++) {
        int cnt = g_count[e];
        if (cnt > MAXR) cnt = MAXR;
        int pad = (cnt + 127) & ~127;
        if (pad > MAXR) pad = MAXR;
        if (tid == 0) g_padded[e] = pad;
        for (int i = cnt + tid; i < pad; i += blockDim.x) {
            g_tok[e * MAXR + i] = 0;
            g_wt [e * MAXR + i] = 0.f;
        }
    }
}

// ---------------------------------------------------------------
// GEMM1 + SwiGLU. Block: 128 m x 64 f-cols (gate+up -> 128 MMA cols).
// 4 warps as 2(m) x 2(n); warp: 64m x 32f with gate AND up accumulators.
__global__ __launch_bounds__(128) void gemm1_kernel()
{
    __shared__ __align__(16) unsigned char smem[2 * 128 * LDT * 2 * 2];  // 40960 B
    __half* As = (__half*)smem;                   // [2][128][LDT]
    __half* Bs = (__half*)(smem + 2 * 128 * LDT * 2);
    float*  Sf = (float*)smem;                    // epilogue alias [128][LDS_F]

    const int e  = blockIdx.y / MTILES;
    const int mt = blockIdx.y % MTILES;
    const int m0 = mt * 128;
    if (m0 >= g_padded[e]) return;
    const int n0 = blockIdx.x * 64;

    const int tid = threadIdx.x;
    const int w   = tid >> 5;
    const int wm  = w >> 1;            // 0..1
    const int wn  = w & 1;             // 0..1

    // per-thread load rows (thread t -> row t)
    const __half* aRow = g_Xh + (size_t)g_tok[e * MAXR + m0 + tid] * D_DIM;
    const int f = (tid < 64) ? (n0 + tid) : (F_DIM + n0 + (tid - 64));
    const __half* bRow = g_Wgu + ((size_t)e * F2_DIM + f) * D_DIM;
    const unsigned aDst0 = smem_u32(As) + tid * (LDT * 2);
    const unsigned bDst0 = smem_u32(Bs) + tid * (LDT * 2);

    auto load_stage = [&](int s, int k0) {
        const __half* a = aRow + k0;
        const __half* b = bRow + k0;
        unsigned ad = aDst0 + s * (128 * LDT * 2);
        unsigned bd = bDst0 + s * (128 * LDT * 2);
        CP16(ad,      a);      CP16(ad + 16, a + 8);
        CP16(ad + 32, a + 16); CP16(ad + 48, a + 24);
        CP16(bd,      b);      CP16(bd + 16, b + 8);
        CP16(bd + 32, b + 16); CP16(bd + 48, b + 24);
    };

    wmma::fragment<wmma::accumulator, 16, 16, 16, float> cg[4][2], cu[4][2];
    #pragma unroll
    for (int i = 0; i < 4; i++)
        #pragma unroll
        for (int j = 0; j < 2; j++) {
            wmma::fill_fragment(cg[i][j], 0.f);
            wmma::fill_fragment(cu[i][j], 0.f);
        }

    load_stage(0, 0);
    CP_COMMIT();
    int s = 0;
    for (int k0 = 0; k0 < D_DIM; k0 += 32) {
        if (k0 + 32 < D_DIM) {
            load_stage(s ^ 1, k0 + 32);
            CP_COMMIT();
            CP_WAIT1();
        } else {
            CP_WAIT0();
        }
        __syncthreads();
        const __half* Ab = As + s * (128 * LDT);
        const __half* Bb = Bs + s * (128 * LDT);
        #pragma unroll
        for (int kk = 0; kk < 32; kk += 16) {
            wmma::fragment<wmma::matrix_a, 16, 16, 16, __half, wmma::row_major> a[4];
            wmma::fragment<wmma::matrix_b, 16, 16, 16, __half, wmma::col_major> bg[2], bu[2];
            #pragma unroll
            for (int i = 0; i < 4; i++)
                wmma::load_matrix_sync(a[i], Ab + (wm * 64 + i * 16) * LDT + kk, LDT);
            #pragma unroll
            for (int j = 0; j < 2; j++) {
                wmma::load_matrix_sync(bg[j], Bb + (wn * 32 + j * 16) * LDT + kk, LDT);
                wmma::load_matrix_sync(bu[j], Bb + (64 + wn * 32 + j * 16) * LDT + kk, LDT);
            }
            #pragma unroll
            for (int i = 0; i < 4; i++)
                #pragma unroll
                for (int j = 0; j < 2; j++) {
                    wmma::mma_sync(cg[i][j], a[i], bg[j], cg[i][j]);
                    wmma::mma_sync(cu[i][j], a[i], bu[j], cu[i][j]);
                }
        }
        __syncthreads();
        s ^= 1;
    }

    // SwiGLU in regs (identical fragment layouts), stage through smem, fp16 out
    #pragma unroll
    for (int i = 0; i < 4; i++)
        #pragma unroll
        for (int j = 0; j < 2; j++) {
            #pragma unroll
            for (int t = 0; t < cg[i][j].num_elements; t++) {
                float g = cg[i][j].x[t];
                float u = cu[i][j].x[t];
                cg[i][j].x[t] = u * g / (1.f + __expf(-g));
            }
            wmma::store_matrix_sync(&Sf[(wm * 64 + i * 16) * LDS_F + wn * 32 + j * 16],
                                    cg[i][j], LDS_F, wmma::mem_row_major);
        }
    __syncthreads();

    __half* hrow = g_h + (size_t)(e * MAXR + m0 + tid) * F_DIM + n0;
    #pragma unroll
    for (int c = 0; c < 8; c++) {
        float*  sp = &Sf[tid * LDS_F + c * 8];
        __half2 h[4];
        h[0] = __floats2half2_rn(sp[0], sp[1]);
        h[1] = __floats2half2_rn(sp[2], sp[3]);
        h[2] = __floats2half2_rn(sp[4], sp[5]);
        h[3] = __floats2half2_rn(sp[6], sp[7]);
        *(uint4*)(hrow + c * 8) = *(uint4*)h;
    }
}

// ---------------------------------------------------------------
// GEMM2: out[tok,n] += w * (h . Wd^T). Block 128 m x 128 n, 4 warps 2x2 of 64x64.
__global__ __launch_bounds__(128) void gemm2_kernel(float* __restrict__ out)
{
    __shared__ __align__(16) unsigned char smem[2 * 128 * LDT * 2 * 2];  // 40960 B
    __half* As = (__half*)smem;
    __half* Bs = (__half*)(smem + 2 * 128 * LDT * 2);
    float*  Sf = (float*)smem;

    const int e  = blockIdx.y / MTILES;
    const int mt = blockIdx.y % MTILES;
    const int m0 = mt * 128;
    if (m0 >= g_padded[e]) return;
    const int n0 = blockIdx.x * 128;

    const int tid = threadIdx.x;
    const int w   = tid >> 5;
    const int wm  = w >> 1;
    const int wn  = w & 1;

    const __half* aRow = g_h  + (size_t)(e * MAXR + m0 + tid) * F_DIM;
    const __half* bRow = g_Wd + ((size_t)e * D_DIM + n0 + tid) * F_DIM;
    const unsigned aDst0 = smem_u32(As) + tid * (LDT * 2);
    const unsigned bDst0 = smem_u32(Bs) + tid * (LDT * 2);

    auto load_stage = [&](int s, int k0) {
        const __half* a = aRow + k0;
        const __half* b = bRow + k0;
        unsigned ad = aDst0 + s * (128 * LDT * 2);
        unsigned bd = bDst0 + s * (128 * LDT * 2);
        CP16(ad,      a);      CP16(ad + 16, a + 8);
        CP16(ad + 32, a + 16); CP16(ad + 48, a + 24);
        CP16(bd,      b);      CP16(bd + 16, b + 8);
        CP16(bd + 32, b + 16); CP16(bd + 48, b + 24);
    };

    wmma::fragment<wmma::accumulator, 16, 16, 16, float> c[4][4];
    #pragma unroll
    for (int i = 0; i < 4; i++)
        #pragma unroll
        for (int j = 0; j < 4; j++)
            wmma::fill_fragment(c[i][j], 0.f);

    load_stage(0, 0);
    CP_COMMIT();
    int s = 0;
    for (int k0 = 0; k0 < F_DIM; k0 += 32) {
        if (k0 + 32 < F_DIM) {
            load_stage(s ^ 1, k0 + 32);
            CP_COMMIT();
            CP_WAIT1();
        } else {
            CP_WAIT0();
        }
        __syncthreads();
        const __half* Ab = As + s * (128 * LDT);
        const __half* Bb = Bs + s * (128 * LDT);
        #pragma unroll
        for (int kk = 0; kk < 32; kk += 16) {
            wmma::fragment<wmma::matrix_a, 16, 16, 16, __half, wmma::row_major> a[4];
            wmma::fragment<wmma::matrix_b, 16, 16, 16, __half, wmma::col_major> b[4];
            #pragma unroll
            for (int i = 0; i < 4; i++)
                wmma::load_matrix_sync(a[i], Ab + (wm * 64 + i * 16) * LDT + kk, LDT);
            #pragma unroll
            for (int j = 0; j < 4; j++)
                wmma::load_matrix_sync(b[j], Bb + (wn * 64 + j * 16) * LDT + kk, LDT);
            #pragma unroll
            for (int i = 0; i < 4; i++)
                #pragma unroll
                for (int j = 0; j < 4; j++)
                    wmma::mma_sync(c[i][j], a[i], b[j], c[i][j]);
        }
        __syncthreads();
        s ^= 1;
    }

    // Epilogue: two 64-col passes through Sf, scale by routing weight, atomicAdd.
    const float wgt = g_wt[e * MAXR + m0 + tid];
    const int   tok = g_tok[e * MAXR + m0 + tid];
    #pragma unroll
    for (int p = 0; p < 2; p++) {
        if (wn == p) {
            #pragma unroll
            for (int i = 0; i < 4; i++)
                #pragma unroll
                for (int j = 0; j < 4; j++)
                    wmma::store_matrix_sync(&Sf[(wm * 64 + i * 16) * LDS_F + j * 16],
                                            c[i][j], LDS_F, wmma::mem_row_major);
        }
        __syncthreads();
        if (wgt != 0.f) {
            float* o = out + (size_t)tok * D_DIM + n0 + p * 64;
            #pragma unroll
            for (int cc = 0; cc < 64; cc++)
                atomicAdd(o + cc, wgt * Sf[tid * LDS_F + cc]);
        }
        __syncthreads();
    }
}

// ---------------------------------------------------------------
extern "C" void kernel_launch(void* const* d_in, const int* in_sizes, int n_in,
                              void* d_out, int out_size) {
    const float* X = nullptr; const float* RW = nullptr;
    const float* WGU = nullptr; const float* WD = nullptr;
    const int* SEL = nullptr;
    for (int i = 0; i < n_in; i++) {
        long long n = in_sizes[i];
        if (n == (long long)T_TOK * D_DIM)               X   = (const float*)d_in[i];
        else if (n == (long long)E_NUM * F2_DIM * D_DIM) WGU = (const float*)d_in[i];
        else if (n == (long long)E_NUM * D_DIM * F_DIM)  WD  = (const float*)d_in[i];
        else if (n == (long long)T_TOK * K_TOP) {
            if (!RW) RW = (const float*)d_in[i];
            else     SEL = (const int*)d_in[i];
        }
    }
    float* out = (float*)d_out;

    __half* Xh;  cudaGetSymbolAddress((void**)&Xh,  g_Xh);
    __half* Wgu; cudaGetSymbolAddress((void**)&Wgu, g_Wgu);
    __half* Wd;  cudaGetSymbolAddress((void**)&Wd,  g_Wd);

    zero_kernel<<<1024, 256>>>(out, T_TOK * D_DIM);
    route_kernel<<<1, 256>>>(SEL, RW);
    cvt_kernel<<<2048, 256>>>(X,   Xh,  T_TOK * D_DIM);
    cvt_kernel<<<4096, 256>>>(WGU, Wgu, E_NUM * F2_DIM * D_DIM);
    cvt_kernel<<<4096, 256>>>(WD,  Wd,  E_NUM * D_DIM * F_DIM);
    gemm1_kernel<<<dim3(F_DIM / 64, E_NUM * MTILES), 128>>>();
    gemm2_kernel<<<dim3(D_DIM / 128, E_NUM * MTILES), 128>>>(out);
}